// round 6
// baseline (speedup 1.0000x reference)
#include <cuda_runtime.h>
#include <cstddef>

// Monarch embedding, analytically folded:
//   out[tok][kr*32+o] = (kr&1 == s) ? L[v*16 + kr/2] * R[(kr*32 + c)*32 + o] : 0
//   v = x[tok], k = v/786, s = k>>5, c = k&31.
//
// R6: persistent pipelined CTAs. Grid 1024 x 256thr, 4 iterations x 4 tokens
// per CTA (single wave at 7 CTAs/SM). Depth-2 software pipeline: x prefetched
// two iters ahead, L gathers for iter j+1 issued at top of iter j -> the
// serial x->L L2-latency chain is paid once per CTA instead of once per wave
// of one-shot CTAs. Body: branch-free SEL parity mask, L1-hot R float4 loads,
// fully-coalesced float4 stores (4 x 128B lines per warp-token).
// Warps parity-pure: warp w -> p=w>>2, rows kr = 2*(4*(w&3)+l/8) + p.

#define GRID_CTAS  1024
#define NITER      4            // 4096 token-blocks / 1024 CTAs
#define BLK_STRIDE 1024         // token-block stride between iterations

__global__ void __launch_bounds__(256, 7) monarch_embed_kernel(
    const int* __restrict__ x,
    const float* __restrict__ L,
    const float* __restrict__ R,
    float* __restrict__ out)
{
    const int tid = threadIdx.x;
    const int w   = tid >> 5;
    const int l   = tid & 31;
    const int p   = w >> 2;                 // warp parity (0/1)
    const int q   = w & 3;
    const int r   = l >> 3;
    const int o   = (l & 7) << 2;
    const int i   = (q << 2) + r;           // 0..15
    const int kr  = (i << 1) + p;           // 0..31
    const int slot = (kr << 5) + o;

    const int bid = blockIdx.x;
    const int4* xp = reinterpret_cast<const int4*>(x) + bid;  // one int4 = 4 tokens

    // ---- prologue: iter-0 chain + iter-1 x in flight ----
    int4 xc = __ldg(xp);
    float lv[4];
    lv[0] = __ldg(&L[(size_t)xc.x * 16 + i]);
    lv[1] = __ldg(&L[(size_t)xc.y * 16 + i]);
    lv[2] = __ldg(&L[(size_t)xc.z * 16 + i]);
    lv[3] = __ldg(&L[(size_t)xc.w * 16 + i]);
    int4 xn = __ldg(xp + BLK_STRIDE);

    float* ob = out + (size_t)bid * 4096 + slot;

#pragma unroll 1
    for (int j = 0; j < NITER; j++) {
        // Fire next-iteration loads first (producers already resolved).
        const int nn = (j + 2 < NITER) ? (j + 2) : (NITER - 1);   // clamp: in-bounds
        int4  xnn  = __ldg(xp + nn * BLK_STRIDE);
        float lvn0 = __ldg(&L[(size_t)xn.x * 16 + i]);
        float lvn1 = __ldg(&L[(size_t)xn.y * 16 + i]);
        float lvn2 = __ldg(&L[(size_t)xn.z * 16 + i]);
        float lvn3 = __ldg(&L[(size_t)xn.w * 16 + i]);

        // Consume current iteration.
        const int vs[4] = {xc.x, xc.y, xc.z, xc.w};
#pragma unroll
        for (int t = 0; t < 4; t++) {
            const int k = vs[t] / 786;
            const int s = k >> 5;
            const int c = k & 31;
            const float4 r4 = *reinterpret_cast<const float4*>(
                &R[((size_t)((kr << 5) + c) << 5) + o]);
            const float lvv = (s == p) ? lv[t] : 0.0f;   // SEL, no branch
            const float4 res = make_float4(lvv * r4.x, lvv * r4.y,
                                           lvv * r4.z, lvv * r4.w);
            *reinterpret_cast<float4*>(ob + (size_t)t * 1024) = res;
        }

        // Rotate pipeline registers.
        xc = xn;  xn = xnn;
        lv[0] = lvn0; lv[1] = lvn1; lv[2] = lvn2; lv[3] = lvn3;
        ob += (size_t)BLK_STRIDE * 4096;     // next iteration's output block
    }
}

extern "C" void kernel_launch(void* const* d_in, const int* in_sizes, int n_in,
                              void* d_out, int out_size) {
    const int*   x = (const int*)  d_in[0];   // (8, 2048) int32
    const float* L = (const float*)d_in[1];   // (64, 786, 16) f32
    const float* R = (const float*)d_in[2];   // (32, 32, 32) f32
    // d_in[3] = p : analytically folded (perfect_shuffle(64, 1024))

    monarch_embed_kernel<<<GRID_CTAS, 256>>>(x, L, R, (float*)d_out);
}